// round 15
// baseline (speedup 1.0000x reference)
#include <cuda_runtime.h>
#include <cuda_bf16.h>
#include <cstdint>

#define N_NODES 50000
#define N_EDGES 800000
#define HID 64
#define CAT_DIM 256
#define CSR_MAX (N_EDGES + 7 * N_NODES + 16)   // padded CSR capacity
#define SCAN_BLOCKS 196                        // 196*256 = 50176 >= N_NODES

// ------------------------- device scratch (static, alloc-free) ----------------
__device__ int   g_cnt_in_i[N_NODES];
__device__ int   g_cnt_out_i[N_NODES];
__device__ float g_dout_is[N_NODES + 1];   // +1 zero entry for CSR pad index
__device__ float g_din_is[N_NODES];
__device__ int   g_row_ptr[N_NODES + 1];
__device__ int   g_cursor[N_NODES];
__device__ int   g_blk_sums[SCAN_BLOCKS];
__device__ int   g_blk_off[SCAN_BLOCKS];
__device__ __align__(16) int g_csr_src[CSR_MAX];
__device__ float g_y[(size_t)(N_NODES + 1) * HID];   // +1 zero row for CSR padding
__device__ float g_cat[(size_t)N_NODES * CAT_DIM];   // JK concat buffer [N,256]

// ------------------------- init: zero counts + prefill CSR + pad rows ----------
__global__ void k_init() {
    int i = blockIdx.x * blockDim.x + threadIdx.x;
    if (i < CSR_MAX / 4)
        ((int4*)g_csr_src)[i] = make_int4(N_NODES, N_NODES, N_NODES, N_NODES);
    if (i < N_NODES) { g_cnt_in_i[i] = 0; g_cnt_out_i[i] = 0; }
    if (i < HID / 4)
        *(float4*)(g_y + (size_t)N_NODES * HID + i * 4) = make_float4(0.f, 0.f, 0.f, 0.f);
    if (i == 0) g_dout_is[N_NODES] = 0.f;   // pad entry
}

// 4 edges per thread: int4 index loads -> MLP~4, 8 independent REDs in flight.
__global__ void k_deg_count(const int* __restrict__ src, const int* __restrict__ dst) {
    int t = blockIdx.x * blockDim.x + threadIdx.x;
    if (t >= N_EDGES / 4) return;
    int4 s = __ldg((const int4*)src + t);
    int4 d = __ldg((const int4*)dst + t);
    atomicAdd(&g_cnt_out_i[s.x], 1);
    atomicAdd(&g_cnt_out_i[s.y], 1);
    atomicAdd(&g_cnt_out_i[s.z], 1);
    atomicAdd(&g_cnt_out_i[s.w], 1);
    atomicAdd(&g_cnt_in_i[d.x], 1);
    atomicAdd(&g_cnt_in_i[d.y], 1);
    atomicAdd(&g_cnt_in_i[d.z], 1);
    atomicAdd(&g_cnt_in_i[d.w], 1);
}

// --- hierarchical scan of padded in-degrees -> row_ptr -------------------------
__global__ __launch_bounds__(256) void k_scan1() {
    __shared__ int sh[256];
    int t = threadIdx.x;
    int i = blockIdx.x * 256 + t;
    int c = (i < N_NODES) ? ((g_cnt_in_i[i] + 7) & ~7) : 0;
    sh[t] = c;
    __syncthreads();
    #pragma unroll
    for (int off = 1; off < 256; off <<= 1) {
        int a = (t >= off) ? sh[t - off] : 0;
        __syncthreads();
        sh[t] += a;
        __syncthreads();
    }
    if (t == 255) g_blk_sums[blockIdx.x] = sh[255];
    if (i < N_NODES) g_row_ptr[i] = sh[t] - c;   // exclusive within block
}

__global__ __launch_bounds__(256) void k_scan2() {
    __shared__ int sh[256];
    int t = threadIdx.x;
    int v = (t < SCAN_BLOCKS) ? g_blk_sums[t] : 0;
    sh[t] = v;
    __syncthreads();
    #pragma unroll
    for (int off = 1; off < 256; off <<= 1) {
        int a = (t >= off) ? sh[t - off] : 0;
        __syncthreads();
        sh[t] += a;
        __syncthreads();
    }
    if (t < SCAN_BLOCKS) g_blk_off[t] = sh[t] - v;   // exclusive
    if (t == 255) g_row_ptr[N_NODES] = sh[255];      // grand total
}

__global__ __launch_bounds__(256) void k_scan3() {
    int i = blockIdx.x * 256 + threadIdx.x;
    if (i >= N_NODES) return;
    int rp = g_row_ptr[i] + g_blk_off[blockIdx.x];
    g_row_ptr[i] = rp;
    g_cursor[i]  = rp;
    g_din_is[i]  = rsqrtf((float)max(g_cnt_in_i[i], 1));
    g_dout_is[i] = rsqrtf((float)max(g_cnt_out_i[i], 1));
}

// 4 edges per thread: overlapped ATOMG round-trips.
__global__ void k_csr_fill(const int* __restrict__ src, const int* __restrict__ dst) {
    int t = blockIdx.x * blockDim.x + threadIdx.x;
    if (t >= N_EDGES / 4) return;
    int4 s = __ldg((const int4*)src + t);
    int4 d = __ldg((const int4*)dst + t);
    int p0 = atomicAdd(&g_cursor[d.x], 1);
    int p1 = atomicAdd(&g_cursor[d.y], 1);
    int p2 = atomicAdd(&g_cursor[d.z], 1);
    int p3 = atomicAdd(&g_cursor[d.w], 1);
    g_csr_src[p0] = s.x;
    g_csr_src[p1] = s.y;
    g_csr_src[p2] = s.z;
    g_csr_src[p3] = s.w;
}

// ------------------------- scalar-FFMA GEMM: Y[n,64] = X[n,K] @ W[K,64] --------
// R11 design (best measured): 64x64 tile, BK=64, 256 threads, 4x4 per thread.
template<int K>
__global__ __launch_bounds__(256)
void k_gemm(const float* __restrict__ X, int ldx,
            const float* __restrict__ W,
            float* __restrict__ Y, int n)
{
    __shared__ float Xs[64][68];
    __shared__ float Ws[64][64];

    const int tid  = threadIdx.x;
    const int row0 = blockIdx.x * 64;
    const int r0   = (tid >> 4) << 2;   // 0..60
    const int c0   = (tid & 15) << 2;   // 0..60

    float acc[4][4];
    #pragma unroll
    for (int i = 0; i < 4; ++i)
        #pragma unroll
        for (int j = 0; j < 4; ++j) acc[i][j] = 0.f;

    for (int kk = 0; kk < K; kk += 64) {
        #pragma unroll
        for (int j = 0; j < 4; ++j) {
            int idx = tid + j * 256;          // 0..1023 float4 slots
            int r   = idx >> 4;
            int c4  = (idx & 15) << 2;
            int row = row0 + r;
            float4 v = make_float4(0.f, 0.f, 0.f, 0.f);
            if (row < n)
                v = *(const float4*)(X + (size_t)row * ldx + kk + c4);
            *(float4*)&Xs[r][c4] = v;
            *(float4*)&Ws[r][c4] = *(const float4*)(W + (size_t)(kk + r) * 64 + c4);
        }
        __syncthreads();

        #pragma unroll
        for (int k = 0; k < 64; ++k) {
            float4 wv = *(const float4*)&Ws[k][c0];
            float a0 = Xs[r0 + 0][k];
            float a1 = Xs[r0 + 1][k];
            float a2 = Xs[r0 + 2][k];
            float a3 = Xs[r0 + 3][k];
            acc[0][0] += a0 * wv.x; acc[0][1] += a0 * wv.y; acc[0][2] += a0 * wv.z; acc[0][3] += a0 * wv.w;
            acc[1][0] += a1 * wv.x; acc[1][1] += a1 * wv.y; acc[1][2] += a1 * wv.z; acc[1][3] += a1 * wv.w;
            acc[2][0] += a2 * wv.x; acc[2][1] += a2 * wv.y; acc[2][2] += a2 * wv.z; acc[2][3] += a2 * wv.w;
            acc[3][0] += a3 * wv.x; acc[3][1] += a3 * wv.y; acc[3][2] += a3 * wv.z; acc[3][3] += a3 * wv.w;
        }
        __syncthreads();
    }

    #pragma unroll
    for (int i = 0; i < 4; ++i) {
        int row = row0 + r0 + i;
        if (row < n) {
            float4 o = make_float4(acc[i][0], acc[i][1], acc[i][2], acc[i][3]);
            *(float4*)(Y + (size_t)row * 64 + c0) = o;
        }
    }
}

// ------------------------- pull aggregation (MLP=8) -----------------------------
// RELU/DOUT layer path: out = relu( din_is[n] * sum_e dout_is[s]*y[s] + bias )
// final path:           out = sum_e y[s] + bias
template<bool RELU, bool DOUT>
__global__ __launch_bounds__(256)
void k_pull(const float* __restrict__ bias, float* __restrict__ outp, int ldo)
{
    int t = blockIdx.x * blockDim.x + threadIdx.x;
    int node = t >> 4;
    if (node >= N_NODES) return;
    int lane4 = (t & 15) << 2;

    int beg = __ldg(&g_row_ptr[node]);
    int end = __ldg(&g_row_ptr[node + 1]);

    float4 accA = make_float4(0.f, 0.f, 0.f, 0.f);
    float4 accB = make_float4(0.f, 0.f, 0.f, 0.f);

    for (int i = beg; i < end; i += 8) {
        int4 sA = __ldg((const int4*)&g_csr_src[i]);
        int4 sB = __ldg((const int4*)&g_csr_src[i + 4]);
        const float* base = g_y + lane4;
        float4 v0 = *(const float4*)(base + (size_t)sA.x * HID);
        float4 v1 = *(const float4*)(base + (size_t)sA.y * HID);
        float4 v2 = *(const float4*)(base + (size_t)sA.z * HID);
        float4 v3 = *(const float4*)(base + (size_t)sA.w * HID);
        float4 v4 = *(const float4*)(base + (size_t)sB.x * HID);
        float4 v5 = *(const float4*)(base + (size_t)sB.y * HID);
        float4 v6 = *(const float4*)(base + (size_t)sB.z * HID);
        float4 v7 = *(const float4*)(base + (size_t)sB.w * HID);
        if (DOUT) {
            float s0 = __ldg(&g_dout_is[sA.x]);
            float s1 = __ldg(&g_dout_is[sA.y]);
            float s2 = __ldg(&g_dout_is[sA.z]);
            float s3 = __ldg(&g_dout_is[sA.w]);
            float s4 = __ldg(&g_dout_is[sB.x]);
            float s5 = __ldg(&g_dout_is[sB.y]);
            float s6 = __ldg(&g_dout_is[sB.z]);
            float s7 = __ldg(&g_dout_is[sB.w]);
            accA.x = fmaf(v0.x, s0, accA.x); accA.y = fmaf(v0.y, s0, accA.y);
            accA.z = fmaf(v0.z, s0, accA.z); accA.w = fmaf(v0.w, s0, accA.w);
            accA.x = fmaf(v1.x, s1, accA.x); accA.y = fmaf(v1.y, s1, accA.y);
            accA.z = fmaf(v1.z, s1, accA.z); accA.w = fmaf(v1.w, s1, accA.w);
            accA.x = fmaf(v2.x, s2, accA.x); accA.y = fmaf(v2.y, s2, accA.y);
            accA.z = fmaf(v2.z, s2, accA.z); accA.w = fmaf(v2.w, s2, accA.w);
            accA.x = fmaf(v3.x, s3, accA.x); accA.y = fmaf(v3.y, s3, accA.y);
            accA.z = fmaf(v3.z, s3, accA.z); accA.w = fmaf(v3.w, s3, accA.w);
            accB.x = fmaf(v4.x, s4, accB.x); accB.y = fmaf(v4.y, s4, accB.y);
            accB.z = fmaf(v4.z, s4, accB.z); accB.w = fmaf(v4.w, s4, accB.w);
            accB.x = fmaf(v5.x, s5, accB.x); accB.y = fmaf(v5.y, s5, accB.y);
            accB.z = fmaf(v5.z, s5, accB.z); accB.w = fmaf(v5.w, s5, accB.w);
            accB.x = fmaf(v6.x, s6, accB.x); accB.y = fmaf(v6.y, s6, accB.y);
            accB.z = fmaf(v6.z, s6, accB.z); accB.w = fmaf(v6.w, s6, accB.w);
            accB.x = fmaf(v7.x, s7, accB.x); accB.y = fmaf(v7.y, s7, accB.y);
            accB.z = fmaf(v7.z, s7, accB.z); accB.w = fmaf(v7.w, s7, accB.w);
        } else {
            accA.x += (v0.x + v1.x) + (v2.x + v3.x);
            accA.y += (v0.y + v1.y) + (v2.y + v3.y);
            accA.z += (v0.z + v1.z) + (v2.z + v3.z);
            accA.w += (v0.w + v1.w) + (v2.w + v3.w);
            accB.x += (v4.x + v5.x) + (v6.x + v7.x);
            accB.y += (v4.y + v5.y) + (v6.y + v7.y);
            accB.z += (v4.z + v5.z) + (v6.z + v7.z);
            accB.w += (v4.w + v5.w) + (v6.w + v7.w);
        }
    }

    float4 acc = make_float4(accA.x + accB.x, accA.y + accB.y,
                             accA.z + accB.z, accA.w + accB.w);
    float4 bv = *(const float4*)(bias + lane4);
    float4 o;
    if (RELU) {
        float sc = __ldg(&g_din_is[node]);
        o.x = fmaxf(fmaf(acc.x, sc, bv.x), 0.f);
        o.y = fmaxf(fmaf(acc.y, sc, bv.y), 0.f);
        o.z = fmaxf(fmaf(acc.z, sc, bv.z), 0.f);
        o.w = fmaxf(fmaf(acc.w, sc, bv.w), 0.f);
    } else {
        o.x = acc.x + bv.x; o.y = acc.y + bv.y;
        o.z = acc.z + bv.z; o.w = acc.w + bv.w;
    }
    *(float4*)(outp + (size_t)node * ldo + lane4) = o;
}

// ------------------------- launch ----------------------------------------------
extern "C" void kernel_launch(void* const* d_in, const int* in_sizes, int n_in,
                              void* d_out, int out_size)
{
    const float* feat  = (const float*)d_in[0];
    const int*   src   = (const int*)d_in[1];
    const int*   dst   = (const int*)d_in[2];
    const float* W[4]  = { (const float*)d_in[3], (const float*)d_in[5],
                           (const float*)d_in[7], (const float*)d_in[9] };
    const float* B[4]  = { (const float*)d_in[4], (const float*)d_in[6],
                           (const float*)d_in[8], (const float*)d_in[10] };
    const float* W_mlp = (const float*)d_in[11];
    const float* b_mlp = (const float*)d_in[12];
    float* out = (float*)d_out;

    float *cat_p = nullptr, *y_p = nullptr;
    cudaGetSymbolAddress((void**)&cat_p, g_cat);
    cudaGetSymbolAddress((void**)&y_p, g_y);

    const int T = 256;
    const int gE4   = (N_EDGES / 4 + T - 1) / T;
    const int gInit = (CSR_MAX / 4 + T - 1) / T;
    const int gPull = (N_NODES * 16 + T - 1) / T;
    const int gGemm = (N_NODES + 63) / 64;

    // CSR build; layer-0 GEMM in slot 4 (profiler captures launch #4)
    k_init<<<gInit, T>>>();                       // 1
    k_deg_count<<<gE4, T>>>(src, dst);            // 2
    k_scan1<<<SCAN_BLOCKS, 256>>>();              // 3
    k_gemm<256><<<gGemm, T>>>(feat, 256, W[0], y_p, N_NODES);   // 4 (profiled)
    k_scan2<<<1, 256>>>();                        // 5
    k_scan3<<<SCAN_BLOCKS, 256>>>();              // 6
    k_csr_fill<<<gE4, T>>>(src, dst);             // 7

    // layer 0 aggregation
    k_pull<true, true><<<gPull, T>>>(B[0], cat_p + 0 * HID, CAT_DIM);

    // layers 1..3
    for (int l = 1; l < 4; ++l) {
        k_gemm<64><<<gGemm, T>>>(cat_p + (l - 1) * HID, CAT_DIM, W[l], y_p, N_NODES);
        k_pull<true, true><<<gPull, T>>>(B[l], cat_p + l * HID, CAT_DIM);
    }

    // final: out = segment_sum((cat @ W_mlp)[src]) + b  (linearity reorder)
    k_gemm<256><<<gGemm, T>>>(cat_p, CAT_DIM, W_mlp, y_p, N_NODES);
    k_pull<false, false><<<gPull, T>>>(b_mlp, out, HID);
}

// round 16
// speedup vs baseline: 1.5037x; 1.5037x over previous
#include <cuda_runtime.h>
#include <cuda_bf16.h>
#include <cstdint>

#define N_NODES 50000
#define N_EDGES 800000
#define HID 64
#define CAT_DIM 256
#define CSR_MAX (N_EDGES + 7 * N_NODES + 16)   // padded CSR capacity
#define SCAN_BLOCKS 196                        // 196*256 = 50176 >= N_NODES

// ------------------------- device scratch (static, alloc-free) ----------------
__device__ int   g_cnt_in_i[N_NODES];
__device__ int   g_cnt_out_i[N_NODES];
__device__ float g_dout_is[N_NODES + 1];   // +1 zero entry for CSR pad index
__device__ float g_din_is[N_NODES];
__device__ int   g_row_ptr[N_NODES + 1];
__device__ int   g_cursor[N_NODES];
__device__ int   g_blk_sums[SCAN_BLOCKS];
__device__ int   g_blk_off[SCAN_BLOCKS];
__device__ __align__(16) int g_csr_src[CSR_MAX];
__device__ float g_y[(size_t)(N_NODES + 1) * HID];   // +1 zero row for CSR padding
__device__ float g_cat[(size_t)N_NODES * CAT_DIM];   // JK concat buffer [N,256]

// ------------------------- init: zero counts + prefill CSR + pad rows ----------
__global__ void k_init() {
    int i = blockIdx.x * blockDim.x + threadIdx.x;
    if (i < CSR_MAX / 4)
        ((int4*)g_csr_src)[i] = make_int4(N_NODES, N_NODES, N_NODES, N_NODES);
    if (i < N_NODES) { g_cnt_in_i[i] = 0; g_cnt_out_i[i] = 0; }
    if (i < HID / 4)
        *(float4*)(g_y + (size_t)N_NODES * HID + i * 4) = make_float4(0.f, 0.f, 0.f, 0.f);
    if (i == 0) g_dout_is[N_NODES] = 0.f;   // pad entry
}

// 4 edges per thread: int4 index loads -> MLP~4, 8 independent REDs in flight.
__global__ void k_deg_count(const int* __restrict__ src, const int* __restrict__ dst) {
    int t = blockIdx.x * blockDim.x + threadIdx.x;
    if (t >= N_EDGES / 4) return;
    int4 s = __ldg((const int4*)src + t);
    int4 d = __ldg((const int4*)dst + t);
    atomicAdd(&g_cnt_out_i[s.x], 1);
    atomicAdd(&g_cnt_out_i[s.y], 1);
    atomicAdd(&g_cnt_out_i[s.z], 1);
    atomicAdd(&g_cnt_out_i[s.w], 1);
    atomicAdd(&g_cnt_in_i[d.x], 1);
    atomicAdd(&g_cnt_in_i[d.y], 1);
    atomicAdd(&g_cnt_in_i[d.z], 1);
    atomicAdd(&g_cnt_in_i[d.w], 1);
}

// --- hierarchical scan of padded in-degrees -> row_ptr -------------------------
__global__ __launch_bounds__(256) void k_scan1() {
    __shared__ int sh[256];
    int t = threadIdx.x;
    int i = blockIdx.x * 256 + t;
    int c = (i < N_NODES) ? ((g_cnt_in_i[i] + 7) & ~7) : 0;
    sh[t] = c;
    __syncthreads();
    #pragma unroll
    for (int off = 1; off < 256; off <<= 1) {
        int a = (t >= off) ? sh[t - off] : 0;
        __syncthreads();
        sh[t] += a;
        __syncthreads();
    }
    if (t == 255) g_blk_sums[blockIdx.x] = sh[255];
    if (i < N_NODES) g_row_ptr[i] = sh[t] - c;   // exclusive within block
}

__global__ __launch_bounds__(256) void k_scan2() {
    __shared__ int sh[256];
    int t = threadIdx.x;
    int v = (t < SCAN_BLOCKS) ? g_blk_sums[t] : 0;
    sh[t] = v;
    __syncthreads();
    #pragma unroll
    for (int off = 1; off < 256; off <<= 1) {
        int a = (t >= off) ? sh[t - off] : 0;
        __syncthreads();
        sh[t] += a;
        __syncthreads();
    }
    if (t < SCAN_BLOCKS) g_blk_off[t] = sh[t] - v;   // exclusive
    if (t == 255) g_row_ptr[N_NODES] = sh[255];      // grand total
}

__global__ __launch_bounds__(256) void k_scan3() {
    int i = blockIdx.x * 256 + threadIdx.x;
    if (i >= N_NODES) return;
    int rp = g_row_ptr[i] + g_blk_off[blockIdx.x];
    g_row_ptr[i] = rp;
    g_cursor[i]  = rp;
    g_din_is[i]  = rsqrtf((float)max(g_cnt_in_i[i], 1));
    g_dout_is[i] = rsqrtf((float)max(g_cnt_out_i[i], 1));
}

// 4 edges per thread: overlapped ATOMG round-trips.
__global__ void k_csr_fill(const int* __restrict__ src, const int* __restrict__ dst) {
    int t = blockIdx.x * blockDim.x + threadIdx.x;
    if (t >= N_EDGES / 4) return;
    int4 s = __ldg((const int4*)src + t);
    int4 d = __ldg((const int4*)dst + t);
    int p0 = atomicAdd(&g_cursor[d.x], 1);
    int p1 = atomicAdd(&g_cursor[d.y], 1);
    int p2 = atomicAdd(&g_cursor[d.z], 1);
    int p3 = atomicAdd(&g_cursor[d.w], 1);
    g_csr_src[p0] = s.x;
    g_csr_src[p1] = s.y;
    g_csr_src[p2] = s.z;
    g_csr_src[p3] = s.w;
}

// ------------------------- scalar-FFMA GEMM: Y[n,64] = X[n,K] @ W[K,64] --------
// R11 design (best measured): 64x64 tile, BK=64, 256 threads, 4x4 per thread.
template<int K>
__global__ __launch_bounds__(256)
void k_gemm(const float* __restrict__ X, int ldx,
            const float* __restrict__ W,
            float* __restrict__ Y, int n)
{
    __shared__ float Xs[64][68];
    __shared__ float Ws[64][64];

    const int tid  = threadIdx.x;
    const int row0 = blockIdx.x * 64;
    const int r0   = (tid >> 4) << 2;   // 0..60
    const int c0   = (tid & 15) << 2;   // 0..60

    float acc[4][4];
    #pragma unroll
    for (int i = 0; i < 4; ++i)
        #pragma unroll
        for (int j = 0; j < 4; ++j) acc[i][j] = 0.f;

    for (int kk = 0; kk < K; kk += 64) {
        #pragma unroll
        for (int j = 0; j < 4; ++j) {
            int idx = tid + j * 256;          // 0..1023 float4 slots
            int r   = idx >> 4;
            int c4  = (idx & 15) << 2;
            int row = row0 + r;
            float4 v = make_float4(0.f, 0.f, 0.f, 0.f);
            if (row < n)
                v = *(const float4*)(X + (size_t)row * ldx + kk + c4);
            *(float4*)&Xs[r][c4] = v;
            *(float4*)&Ws[r][c4] = *(const float4*)(W + (size_t)(kk + r) * 64 + c4);
        }
        __syncthreads();

        #pragma unroll
        for (int k = 0; k < 64; ++k) {
            float4 wv = *(const float4*)&Ws[k][c0];
            float a0 = Xs[r0 + 0][k];
            float a1 = Xs[r0 + 1][k];
            float a2 = Xs[r0 + 2][k];
            float a3 = Xs[r0 + 3][k];
            acc[0][0] += a0 * wv.x; acc[0][1] += a0 * wv.y; acc[0][2] += a0 * wv.z; acc[0][3] += a0 * wv.w;
            acc[1][0] += a1 * wv.x; acc[1][1] += a1 * wv.y; acc[1][2] += a1 * wv.z; acc[1][3] += a1 * wv.w;
            acc[2][0] += a2 * wv.x; acc[2][1] += a2 * wv.y; acc[2][2] += a2 * wv.z; acc[2][3] += a2 * wv.w;
            acc[3][0] += a3 * wv.x; acc[3][1] += a3 * wv.y; acc[3][2] += a3 * wv.z; acc[3][3] += a3 * wv.w;
        }
        __syncthreads();
    }

    #pragma unroll
    for (int i = 0; i < 4; ++i) {
        int row = row0 + r0 + i;
        if (row < n) {
            float4 o = make_float4(acc[i][0], acc[i][1], acc[i][2], acc[i][3]);
            *(float4*)(Y + (size_t)row * 64 + c0) = o;
        }
    }
}

// ------------------------- pull aggregation (MLP=8) -----------------------------
// RELU/DOUT layer path: out = relu( din_is[n] * sum_e dout_is[s]*y[s] + bias )
// final path:           out = sum_e y[s] + bias
template<bool RELU, bool DOUT>
__global__ __launch_bounds__(256)
void k_pull(const float* __restrict__ bias, float* __restrict__ outp, int ldo)
{
    int t = blockIdx.x * blockDim.x + threadIdx.x;
    int node = t >> 4;
    if (node >= N_NODES) return;
    int lane4 = (t & 15) << 2;

    int beg = __ldg(&g_row_ptr[node]);
    int end = __ldg(&g_row_ptr[node + 1]);

    float4 accA = make_float4(0.f, 0.f, 0.f, 0.f);
    float4 accB = make_float4(0.f, 0.f, 0.f, 0.f);

    for (int i = beg; i < end; i += 8) {
        int4 sA = __ldg((const int4*)&g_csr_src[i]);
        int4 sB = __ldg((const int4*)&g_csr_src[i + 4]);
        const float* base = g_y + lane4;
        float4 v0 = *(const float4*)(base + (size_t)sA.x * HID);
        float4 v1 = *(const float4*)(base + (size_t)sA.y * HID);
        float4 v2 = *(const float4*)(base + (size_t)sA.z * HID);
        float4 v3 = *(const float4*)(base + (size_t)sA.w * HID);
        float4 v4 = *(const float4*)(base + (size_t)sB.x * HID);
        float4 v5 = *(const float4*)(base + (size_t)sB.y * HID);
        float4 v6 = *(const float4*)(base + (size_t)sB.z * HID);
        float4 v7 = *(const float4*)(base + (size_t)sB.w * HID);
        if (DOUT) {
            float s0 = __ldg(&g_dout_is[sA.x]);
            float s1 = __ldg(&g_dout_is[sA.y]);
            float s2 = __ldg(&g_dout_is[sA.z]);
            float s3 = __ldg(&g_dout_is[sA.w]);
            float s4 = __ldg(&g_dout_is[sB.x]);
            float s5 = __ldg(&g_dout_is[sB.y]);
            float s6 = __ldg(&g_dout_is[sB.z]);
            float s7 = __ldg(&g_dout_is[sB.w]);
            accA.x = fmaf(v0.x, s0, accA.x); accA.y = fmaf(v0.y, s0, accA.y);
            accA.z = fmaf(v0.z, s0, accA.z); accA.w = fmaf(v0.w, s0, accA.w);
            accA.x = fmaf(v1.x, s1, accA.x); accA.y = fmaf(v1.y, s1, accA.y);
            accA.z = fmaf(v1.z, s1, accA.z); accA.w = fmaf(v1.w, s1, accA.w);
            accA.x = fmaf(v2.x, s2, accA.x); accA.y = fmaf(v2.y, s2, accA.y);
            accA.z = fmaf(v2.z, s2, accA.z); accA.w = fmaf(v2.w, s2, accA.w);
            accA.x = fmaf(v3.x, s3, accA.x); accA.y = fmaf(v3.y, s3, accA.y);
            accA.z = fmaf(v3.z, s3, accA.z); accA.w = fmaf(v3.w, s3, accA.w);
            accB.x = fmaf(v4.x, s4, accB.x); accB.y = fmaf(v4.y, s4, accB.y);
            accB.z = fmaf(v4.z, s4, accB.z); accB.w = fmaf(v4.w, s4, accB.w);
            accB.x = fmaf(v5.x, s5, accB.x); accB.y = fmaf(v5.y, s5, accB.y);
            accB.z = fmaf(v5.z, s5, accB.z); accB.w = fmaf(v5.w, s5, accB.w);
            accB.x = fmaf(v6.x, s6, accB.x); accB.y = fmaf(v6.y, s6, accB.y);
            accB.z = fmaf(v6.z, s6, accB.z); accB.w = fmaf(v6.w, s6, accB.w);
            accB.x = fmaf(v7.x, s7, accB.x); accB.y = fmaf(v7.y, s7, accB.y);
            accB.z = fmaf(v7.z, s7, accB.z); accB.w = fmaf(v7.w, s7, accB.w);
        } else {
            accA.x += (v0.x + v1.x) + (v2.x + v3.x);
            accA.y += (v0.y + v1.y) + (v2.y + v3.y);
            accA.z += (v0.z + v1.z) + (v2.z + v3.z);
            accA.w += (v0.w + v1.w) + (v2.w + v3.w);
            accB.x += (v4.x + v5.x) + (v6.x + v7.x);
            accB.y += (v4.y + v5.y) + (v6.y + v7.y);
            accB.z += (v4.z + v5.z) + (v6.z + v7.z);
            accB.w += (v4.w + v5.w) + (v6.w + v7.w);
        }
    }

    float4 acc = make_float4(accA.x + accB.x, accA.y + accB.y,
                             accA.z + accB.z, accA.w + accB.w);
    float4 bv = *(const float4*)(bias + lane4);
    float4 o;
    if (RELU) {
        float sc = __ldg(&g_din_is[node]);
        o.x = fmaxf(fmaf(acc.x, sc, bv.x), 0.f);
        o.y = fmaxf(fmaf(acc.y, sc, bv.y), 0.f);
        o.z = fmaxf(fmaf(acc.z, sc, bv.z), 0.f);
        o.w = fmaxf(fmaf(acc.w, sc, bv.w), 0.f);
    } else {
        o.x = acc.x + bv.x; o.y = acc.y + bv.y;
        o.z = acc.z + bv.z; o.w = acc.w + bv.w;
    }
    *(float4*)(outp + (size_t)node * ldo + lane4) = o;
}

// ------------------------- launch ----------------------------------------------
extern "C" void kernel_launch(void* const* d_in, const int* in_sizes, int n_in,
                              void* d_out, int out_size)
{
    const float* feat  = (const float*)d_in[0];
    const int*   src   = (const int*)d_in[1];
    const int*   dst   = (const int*)d_in[2];
    const float* W[4]  = { (const float*)d_in[3], (const float*)d_in[5],
                           (const float*)d_in[7], (const float*)d_in[9] };
    const float* B[4]  = { (const float*)d_in[4], (const float*)d_in[6],
                           (const float*)d_in[8], (const float*)d_in[10] };
    const float* W_mlp = (const float*)d_in[11];
    const float* b_mlp = (const float*)d_in[12];
    float* out = (float*)d_out;

    float *cat_p = nullptr, *y_p = nullptr;
    cudaGetSymbolAddress((void**)&cat_p, g_cat);
    cudaGetSymbolAddress((void**)&y_p, g_y);

    const int T = 256;
    const int gE4   = (N_EDGES / 4 + T - 1) / T;
    const int gInit = (CSR_MAX / 4 + T - 1) / T;
    const int gPull = (N_NODES * 16 + T - 1) / T;
    const int gGemm = (N_NODES + 63) / 64;

    // CSR build; layer-0 GEMM in slot 4 (profiler captures launch #4)
    k_init<<<gInit, T>>>();                       // 1
    k_deg_count<<<gE4, T>>>(src, dst);            // 2
    k_scan1<<<SCAN_BLOCKS, 256>>>();              // 3
    k_gemm<256><<<gGemm, T>>>(feat, 256, W[0], y_p, N_NODES);   // 4 (profiled)
    k_scan2<<<1, 256>>>();                        // 5
    k_scan3<<<SCAN_BLOCKS, 256>>>();              // 6
    k_csr_fill<<<gE4, T>>>(src, dst);             // 7

    // layer 0 aggregation
    k_pull<true, true><<<gPull, T>>>(B[0], cat_p + 0 * HID, CAT_DIM);

    // layers 1..3
    for (int l = 1; l < 4; ++l) {
        k_gemm<64><<<gGemm, T>>>(cat_p + (l - 1) * HID, CAT_DIM, W[l], y_p, N_NODES);
        k_pull<true, true><<<gPull, T>>>(B[l], cat_p + l * HID, CAT_DIM);
    }

    // final: out = segment_sum((cat @ W_mlp)[src]) + b  (linearity reorder)
    k_gemm<256><<<gGemm, T>>>(cat_p, CAT_DIM, W_mlp, y_p, N_NODES);
    k_pull<false, false><<<gPull, T>>>(b_mlp, out, HID);
}

// round 17
// speedup vs baseline: 1.6567x; 1.1017x over previous
#include <cuda_runtime.h>
#include <cuda_bf16.h>
#include <cstdint>

#define N_NODES 50000
#define N_EDGES 800000
#define HID 64
#define CAT_DIM 256
#define CSR_MAX (N_EDGES + 7 * N_NODES + 16)   // padded CSR capacity
#define SCAN_BLOCKS 196                        // 196*256 = 50176 >= N_NODES

// ------------------------- device scratch (static, alloc-free) ----------------
__device__ int   g_cnt_in_i[N_NODES];
__device__ int   g_cnt_out_i[N_NODES];
__device__ float g_dout_is[N_NODES + 1];   // +1 zero entry for CSR pad index
__device__ float g_din_is[N_NODES];
__device__ int   g_row_ptr[N_NODES + 1];
__device__ int   g_cursor[N_NODES];
__device__ int   g_blk_sums[SCAN_BLOCKS];
__device__ int   g_blk_off[SCAN_BLOCKS];
__device__ __align__(16) int g_csr_src[CSR_MAX];
__device__ float g_y[(size_t)(N_NODES + 1) * HID];   // +1 zero row for CSR padding
__device__ float g_cat[(size_t)N_NODES * CAT_DIM];   // JK concat buffer [N,256]

// ------------------------- tf32 helpers ----------------------------------------
__device__ __forceinline__ unsigned f2tf32(float x) {
    unsigned r; asm("cvt.rna.tf32.f32 %0, %1;" : "=r"(r) : "f"(x)); return r;
}
__device__ __forceinline__ void mma_tf32(float* d, const unsigned* a, const unsigned* b) {
    asm volatile(
        "mma.sync.aligned.m16n8k8.row.col.f32.tf32.tf32.f32 "
        "{%0,%1,%2,%3}, {%4,%5,%6,%7}, {%8,%9}, {%0,%1,%2,%3};"
        : "+f"(d[0]), "+f"(d[1]), "+f"(d[2]), "+f"(d[3])
        : "r"(a[0]), "r"(a[1]), "r"(a[2]), "r"(a[3]), "r"(b[0]), "r"(b[1]));
}

// ------------------------- init: zero counts + prefill CSR + pad rows ----------
__global__ void k_init() {
    int i = blockIdx.x * blockDim.x + threadIdx.x;
    if (i < CSR_MAX / 4)
        ((int4*)g_csr_src)[i] = make_int4(N_NODES, N_NODES, N_NODES, N_NODES);
    if (i < N_NODES) { g_cnt_in_i[i] = 0; g_cnt_out_i[i] = 0; }
    if (i < HID / 4)
        *(float4*)(g_y + (size_t)N_NODES * HID + i * 4) = make_float4(0.f, 0.f, 0.f, 0.f);
    if (i == 0) g_dout_is[N_NODES] = 0.f;   // pad entry
}

// 4 edges per thread: int4 index loads -> MLP~4, 8 independent REDs in flight.
__global__ void k_deg_count(const int* __restrict__ src, const int* __restrict__ dst) {
    int t = blockIdx.x * blockDim.x + threadIdx.x;
    if (t >= N_EDGES / 4) return;
    int4 s = __ldg((const int4*)src + t);
    int4 d = __ldg((const int4*)dst + t);
    atomicAdd(&g_cnt_out_i[s.x], 1);
    atomicAdd(&g_cnt_out_i[s.y], 1);
    atomicAdd(&g_cnt_out_i[s.z], 1);
    atomicAdd(&g_cnt_out_i[s.w], 1);
    atomicAdd(&g_cnt_in_i[d.x], 1);
    atomicAdd(&g_cnt_in_i[d.y], 1);
    atomicAdd(&g_cnt_in_i[d.z], 1);
    atomicAdd(&g_cnt_in_i[d.w], 1);
}

// --- hierarchical scan of padded in-degrees -> row_ptr -------------------------
__global__ __launch_bounds__(256) void k_scan1() {
    __shared__ int sh[256];
    int t = threadIdx.x;
    int i = blockIdx.x * 256 + t;
    int c = (i < N_NODES) ? ((g_cnt_in_i[i] + 7) & ~7) : 0;
    sh[t] = c;
    __syncthreads();
    #pragma unroll
    for (int off = 1; off < 256; off <<= 1) {
        int a = (t >= off) ? sh[t - off] : 0;
        __syncthreads();
        sh[t] += a;
        __syncthreads();
    }
    if (t == 255) g_blk_sums[blockIdx.x] = sh[255];
    if (i < N_NODES) g_row_ptr[i] = sh[t] - c;   // exclusive within block
}

__global__ __launch_bounds__(256) void k_scan2() {
    __shared__ int sh[256];
    int t = threadIdx.x;
    int v = (t < SCAN_BLOCKS) ? g_blk_sums[t] : 0;
    sh[t] = v;
    __syncthreads();
    #pragma unroll
    for (int off = 1; off < 256; off <<= 1) {
        int a = (t >= off) ? sh[t - off] : 0;
        __syncthreads();
        sh[t] += a;
        __syncthreads();
    }
    if (t < SCAN_BLOCKS) g_blk_off[t] = sh[t] - v;   // exclusive
    if (t == 255) g_row_ptr[N_NODES] = sh[255];      // grand total
}

__global__ __launch_bounds__(256) void k_scan3() {
    int i = blockIdx.x * 256 + threadIdx.x;
    if (i >= N_NODES) return;
    int rp = g_row_ptr[i] + g_blk_off[blockIdx.x];
    g_row_ptr[i] = rp;
    g_cursor[i]  = rp;
    g_din_is[i]  = rsqrtf((float)max(g_cnt_in_i[i], 1));
    g_dout_is[i] = rsqrtf((float)max(g_cnt_out_i[i], 1));
}

// 4 edges per thread: overlapped ATOMG round-trips.
__global__ void k_csr_fill(const int* __restrict__ src, const int* __restrict__ dst) {
    int t = blockIdx.x * blockDim.x + threadIdx.x;
    if (t >= N_EDGES / 4) return;
    int4 s = __ldg((const int4*)src + t);
    int4 d = __ldg((const int4*)dst + t);
    int p0 = atomicAdd(&g_cursor[d.x], 1);
    int p1 = atomicAdd(&g_cursor[d.y], 1);
    int p2 = atomicAdd(&g_cursor[d.z], 1);
    int p3 = atomicAdd(&g_cursor[d.w], 1);
    g_csr_src[p0] = s.x;
    g_csr_src[p1] = s.y;
    g_csr_src[p2] = s.z;
    g_csr_src[p3] = s.w;
}

// ------------------------- 3xTF32 tensor GEMM: Y[n,64] = X[n,K] @ W[K,64] ------
// Block tile 128x64, BK=16, 256 threads (8 warps = 4m x 2n, warp tile 32x32).
// x = hi + lo tf32 split; D += Ah*Bh + Ah*Bl + Al*Bh  (error ~2^-21, fp32-grade).
// Smem banks: A stride 20 -> bank (4r+k) bijective (conflict-free);
//             W stride 72 -> bank (8k+n) bijective (conflict-free).
template<int K>
__global__ __launch_bounds__(256)
void k_gemm(const float* __restrict__ X, int ldx,
            const float* __restrict__ W,
            float* __restrict__ Y, int n)
{
    __shared__ unsigned Ahi[128][20], Alo[128][20];
    __shared__ unsigned Whi[16][72],  Wlo[16][72];

    const int tid   = threadIdx.x;
    const int lane  = tid & 31;
    const int warp  = tid >> 5;
    const int g     = lane >> 2;     // group id 0..7
    const int t4    = lane & 3;      // thread-in-group 0..3
    const int mbase = (warp & 3) * 32;
    const int nbase = (warp >> 2) * 32;
    const int row0  = blockIdx.x * 128;

    float acc[2][4][4];
    #pragma unroll
    for (int mt = 0; mt < 2; ++mt)
        #pragma unroll
        for (int nt = 0; nt < 4; ++nt)
            #pragma unroll
            for (int e = 0; e < 4; ++e) acc[mt][nt][e] = 0.f;

    for (int kk = 0; kk < K; kk += 16) {
        // X tile 128x16: 512 float4 slots, 2 per thread; hi/lo split on the fly
        #pragma unroll
        for (int j = 0; j < 2; ++j) {
            int slot = tid + j * 256;
            int r    = slot >> 2;
            int c4   = (slot & 3) << 2;
            int row  = row0 + r;
            float4 v = make_float4(0.f, 0.f, 0.f, 0.f);
            if (row < n)
                v = *(const float4*)(X + (size_t)row * ldx + kk + c4);
            unsigned h0 = f2tf32(v.x), h1 = f2tf32(v.y), h2 = f2tf32(v.z), h3 = f2tf32(v.w);
            unsigned l0 = f2tf32(v.x - __uint_as_float(h0));
            unsigned l1 = f2tf32(v.y - __uint_as_float(h1));
            unsigned l2 = f2tf32(v.z - __uint_as_float(h2));
            unsigned l3 = f2tf32(v.w - __uint_as_float(h3));
            *(uint4*)&Ahi[r][c4] = make_uint4(h0, h1, h2, h3);
            *(uint4*)&Alo[r][c4] = make_uint4(l0, l1, l2, l3);
        }
        // W tile 16x64: 256 float4 slots, 1 per thread
        {
            int r  = tid >> 4;
            int c4 = (tid & 15) << 2;
            float4 v = *(const float4*)(W + (size_t)(kk + r) * 64 + c4);
            unsigned h0 = f2tf32(v.x), h1 = f2tf32(v.y), h2 = f2tf32(v.z), h3 = f2tf32(v.w);
            unsigned l0 = f2tf32(v.x - __uint_as_float(h0));
            unsigned l1 = f2tf32(v.y - __uint_as_float(h1));
            unsigned l2 = f2tf32(v.z - __uint_as_float(h2));
            unsigned l3 = f2tf32(v.w - __uint_as_float(h3));
            *(uint4*)&Whi[r][c4] = make_uint4(h0, h1, h2, h3);
            *(uint4*)&Wlo[r][c4] = make_uint4(l0, l1, l2, l3);
        }
        __syncthreads();

        #pragma unroll
        for (int kc = 0; kc < 16; kc += 8) {
            unsigned bh[4][2], bl[4][2];
            #pragma unroll
            for (int nt = 0; nt < 4; ++nt) {
                int bc = nbase + nt * 8 + g;
                bh[nt][0] = Whi[kc + t4][bc];
                bh[nt][1] = Whi[kc + t4 + 4][bc];
                bl[nt][0] = Wlo[kc + t4][bc];
                bl[nt][1] = Wlo[kc + t4 + 4][bc];
            }
            #pragma unroll
            for (int mt = 0; mt < 2; ++mt) {
                int br = mbase + mt * 16;
                unsigned ah[4], al[4];
                ah[0] = Ahi[br + g    ][kc + t4];
                ah[1] = Ahi[br + g + 8][kc + t4];
                ah[2] = Ahi[br + g    ][kc + t4 + 4];
                ah[3] = Ahi[br + g + 8][kc + t4 + 4];
                al[0] = Alo[br + g    ][kc + t4];
                al[1] = Alo[br + g + 8][kc + t4];
                al[2] = Alo[br + g    ][kc + t4 + 4];
                al[3] = Alo[br + g + 8][kc + t4 + 4];
                #pragma unroll
                for (int nt = 0; nt < 4; ++nt) {
                    mma_tf32(acc[mt][nt], ah, bh[nt]);
                    mma_tf32(acc[mt][nt], ah, bl[nt]);
                    mma_tf32(acc[mt][nt], al, bh[nt]);
                }
            }
        }
        __syncthreads();
    }

    // epilogue: D fragment -> rows (g, g+8), cols 2*t4 + {0,1} per 16x8 tile
    #pragma unroll
    for (int mt = 0; mt < 2; ++mt) {
        int rA = row0 + mbase + mt * 16 + g;
        #pragma unroll
        for (int nt = 0; nt < 4; ++nt) {
            int c = nbase + nt * 8 + t4 * 2;
            if (rA < n)
                *(float2*)(Y + (size_t)rA * 64 + c) = make_float2(acc[mt][nt][0], acc[mt][nt][1]);
            if (rA + 8 < n)
                *(float2*)(Y + (size_t)(rA + 8) * 64 + c) = make_float2(acc[mt][nt][2], acc[mt][nt][3]);
        }
    }
}

// ------------------------- pull aggregation (MLP=8) -----------------------------
// RELU/DOUT layer path: out = relu( din_is[n] * sum_e dout_is[s]*y[s] + bias )
// final path:           out = sum_e y[s] + bias
template<bool RELU, bool DOUT>
__global__ __launch_bounds__(256)
void k_pull(const float* __restrict__ bias, float* __restrict__ outp, int ldo)
{
    int t = blockIdx.x * blockDim.x + threadIdx.x;
    int node = t >> 4;
    if (node >= N_NODES) return;
    int lane4 = (t & 15) << 2;

    int beg = __ldg(&g_row_ptr[node]);
    int end = __ldg(&g_row_ptr[node + 1]);

    float4 accA = make_float4(0.f, 0.f, 0.f, 0.f);
    float4 accB = make_float4(0.f, 0.f, 0.f, 0.f);

    for (int i = beg; i < end; i += 8) {
        int4 sA = __ldg((const int4*)&g_csr_src[i]);
        int4 sB = __ldg((const int4*)&g_csr_src[i + 4]);
        const float* base = g_y + lane4;
        float4 v0 = *(const float4*)(base + (size_t)sA.x * HID);
        float4 v1 = *(const float4*)(base + (size_t)sA.y * HID);
        float4 v2 = *(const float4*)(base + (size_t)sA.z * HID);
        float4 v3 = *(const float4*)(base + (size_t)sA.w * HID);
        float4 v4 = *(const float4*)(base + (size_t)sB.x * HID);
        float4 v5 = *(const float4*)(base + (size_t)sB.y * HID);
        float4 v6 = *(const float4*)(base + (size_t)sB.z * HID);
        float4 v7 = *(const float4*)(base + (size_t)sB.w * HID);
        if (DOUT) {
            float s0 = __ldg(&g_dout_is[sA.x]);
            float s1 = __ldg(&g_dout_is[sA.y]);
            float s2 = __ldg(&g_dout_is[sA.z]);
            float s3 = __ldg(&g_dout_is[sA.w]);
            float s4 = __ldg(&g_dout_is[sB.x]);
            float s5 = __ldg(&g_dout_is[sB.y]);
            float s6 = __ldg(&g_dout_is[sB.z]);
            float s7 = __ldg(&g_dout_is[sB.w]);
            accA.x = fmaf(v0.x, s0, accA.x); accA.y = fmaf(v0.y, s0, accA.y);
            accA.z = fmaf(v0.z, s0, accA.z); accA.w = fmaf(v0.w, s0, accA.w);
            accA.x = fmaf(v1.x, s1, accA.x); accA.y = fmaf(v1.y, s1, accA.y);
            accA.z = fmaf(v1.z, s1, accA.z); accA.w = fmaf(v1.w, s1, accA.w);
            accA.x = fmaf(v2.x, s2, accA.x); accA.y = fmaf(v2.y, s2, accA.y);
            accA.z = fmaf(v2.z, s2, accA.z); accA.w = fmaf(v2.w, s2, accA.w);
            accA.x = fmaf(v3.x, s3, accA.x); accA.y = fmaf(v3.y, s3, accA.y);
            accA.z = fmaf(v3.z, s3, accA.z); accA.w = fmaf(v3.w, s3, accA.w);
            accB.x = fmaf(v4.x, s4, accB.x); accB.y = fmaf(v4.y, s4, accB.y);
            accB.z = fmaf(v4.z, s4, accB.z); accB.w = fmaf(v4.w, s4, accB.w);
            accB.x = fmaf(v5.x, s5, accB.x); accB.y = fmaf(v5.y, s5, accB.y);
            accB.z = fmaf(v5.z, s5, accB.z); accB.w = fmaf(v5.w, s5, accB.w);
            accB.x = fmaf(v6.x, s6, accB.x); accB.y = fmaf(v6.y, s6, accB.y);
            accB.z = fmaf(v6.z, s6, accB.z); accB.w = fmaf(v6.w, s6, accB.w);
            accB.x = fmaf(v7.x, s7, accB.x); accB.y = fmaf(v7.y, s7, accB.y);
            accB.z = fmaf(v7.z, s7, accB.z); accB.w = fmaf(v7.w, s7, accB.w);
        } else {
            accA.x += (v0.x + v1.x) + (v2.x + v3.x);
            accA.y += (v0.y + v1.y) + (v2.y + v3.y);
            accA.z += (v0.z + v1.z) + (v2.z + v3.z);
            accA.w += (v0.w + v1.w) + (v2.w + v3.w);
            accB.x += (v4.x + v5.x) + (v6.x + v7.x);
            accB.y += (v4.y + v5.y) + (v6.y + v7.y);
            accB.z += (v4.z + v5.z) + (v6.z + v7.z);
            accB.w += (v4.w + v5.w) + (v6.w + v7.w);
        }
    }

    float4 acc = make_float4(accA.x + accB.x, accA.y + accB.y,
                             accA.z + accB.z, accA.w + accB.w);
    float4 bv = *(const float4*)(bias + lane4);
    float4 o;
    if (RELU) {
        float sc = __ldg(&g_din_is[node]);
        o.x = fmaxf(fmaf(acc.x, sc, bv.x), 0.f);
        o.y = fmaxf(fmaf(acc.y, sc, bv.y), 0.f);
        o.z = fmaxf(fmaf(acc.z, sc, bv.z), 0.f);
        o.w = fmaxf(fmaf(acc.w, sc, bv.w), 0.f);
    } else {
        o.x = acc.x + bv.x; o.y = acc.y + bv.y;
        o.z = acc.z + bv.z; o.w = acc.w + bv.w;
    }
    *(float4*)(outp + (size_t)node * ldo + lane4) = o;
}

// ------------------------- launch ----------------------------------------------
extern "C" void kernel_launch(void* const* d_in, const int* in_sizes, int n_in,
                              void* d_out, int out_size)
{
    const float* feat  = (const float*)d_in[0];
    const int*   src   = (const int*)d_in[1];
    const int*   dst   = (const int*)d_in[2];
    const float* W[4]  = { (const float*)d_in[3], (const float*)d_in[5],
                           (const float*)d_in[7], (const float*)d_in[9] };
    const float* B[4]  = { (const float*)d_in[4], (const float*)d_in[6],
                           (const float*)d_in[8], (const float*)d_in[10] };
    const float* W_mlp = (const float*)d_in[11];
    const float* b_mlp = (const float*)d_in[12];
    float* out = (float*)d_out;

    float *cat_p = nullptr, *y_p = nullptr;
    cudaGetSymbolAddress((void**)&cat_p, g_cat);
    cudaGetSymbolAddress((void**)&y_p, g_y);

    const int T = 256;
    const int gE4   = (N_EDGES / 4 + T - 1) / T;
    const int gInit = (CSR_MAX / 4 + T - 1) / T;
    const int gPull = (N_NODES * 16 + T - 1) / T;
    const int gGemm = (N_NODES + 127) / 128;

    // CSR build; layer-0 GEMM in slot 4 (profiler captures launch #4)
    k_init<<<gInit, T>>>();                       // 1
    k_deg_count<<<gE4, T>>>(src, dst);            // 2
    k_scan1<<<SCAN_BLOCKS, 256>>>();              // 3
    k_gemm<256><<<gGemm, T>>>(feat, 256, W[0], y_p, N_NODES);   // 4 (profiled)
    k_scan2<<<1, 256>>>();                        // 5
    k_scan3<<<SCAN_BLOCKS, 256>>>();              // 6
    k_csr_fill<<<gE4, T>>>(src, dst);             // 7

    // layer 0 aggregation
    k_pull<true, true><<<gPull, T>>>(B[0], cat_p + 0 * HID, CAT_DIM);

    // layers 1..3
    for (int l = 1; l < 4; ++l) {
        k_gemm<64><<<gGemm, T>>>(cat_p + (l - 1) * HID, CAT_DIM, W[l], y_p, N_NODES);
        k_pull<true, true><<<gPull, T>>>(B[l], cat_p + l * HID, CAT_DIM);
    }

    // final: out = segment_sum((cat @ W_mlp)[src]) + b  (linearity reorder)
    k_gemm<256><<<gGemm, T>>>(cat_p, CAT_DIM, W_mlp, y_p, N_NODES);
    k_pull<false, false><<<gPull, T>>>(b_mlp, out, HID);
}